// round 2
// baseline (speedup 1.0000x reference)
#include <cuda_runtime.h>
#include <cstddef>

// ---------------------------------------------------------------------------
// TinyTransformer: B=4, S=2048, D=512, V=32000
// Pipeline: qkv = gather(embed,x) @ qkv_w + b
//           scores = Q @ K^T * scale  (causal lower-triangular blocks only)
//           attn   = softmax(scores)  (masked tail zeroed)
//           out    = attn @ V         (k-tiles truncated at causal boundary)
//           logits = out @ fc_w + fc_b
// ---------------------------------------------------------------------------

#define BATCH 4
#define SEQ   2048
#define DIM   512
#define VOCAB 32000
#define NQKV  1536            // 3*DIM
#define MTOK  8192            // BATCH*SEQ

// Scratch (static device globals — allocation-free per harness rules)
__device__ float g_qkv[(size_t)MTOK * NQKV];            // 50.3 MB
__device__ float g_scores[(size_t)BATCH * SEQ * SEQ];   // 67.1 MB
__device__ float g_attn_out[(size_t)MTOK * DIM];        // 16.8 MB

// ---------------------------------------------------------------------------
// Common SGEMM config: 128x128 block tile, BK=8, 256 threads, 8x8 microtile
// ---------------------------------------------------------------------------

#define GEMM_PROLOGUE()                                                        \
    __shared__ float As[8][128];                                               \
    __shared__ float Bs[8][128];                                               \
    const int tid = threadIdx.x;                                               \
    const int tx = tid & 15;          /* 0..15 -> n microtile */               \
    const int ty = tid >> 4;          /* 0..15 -> m microtile */               \
    const int ar = tid >> 1, ac = (tid & 1) * 4;   /* A tile load coords */    \
    const int br = tid >> 5, bc = (tid & 31) * 4;  /* B tile load coords */    \
    float acc[8][8];                                                           \
    _Pragma("unroll")                                                          \
    for (int i = 0; i < 8; i++)                                                \
        _Pragma("unroll")                                                      \
        for (int j = 0; j < 8; j++) acc[i][j] = 0.f;

#define GEMM_COMPUTE()                                                         \
    __syncthreads();                                                           \
    _Pragma("unroll")                                                          \
    for (int kk = 0; kk < 8; kk++) {                                           \
        float4 a0 = *(const float4*)&As[kk][ty * 8];                           \
        float4 a1 = *(const float4*)&As[kk][ty * 8 + 4];                       \
        float4 b0 = *(const float4*)&Bs[kk][tx * 8];                           \
        float4 b1 = *(const float4*)&Bs[kk][tx * 8 + 4];                       \
        float a[8] = {a0.x, a0.y, a0.z, a0.w, a1.x, a1.y, a1.z, a1.w};         \
        float b[8] = {b0.x, b0.y, b0.z, b0.w, b1.x, b1.y, b1.z, b1.w};         \
        _Pragma("unroll")                                                      \
        for (int i = 0; i < 8; i++)                                            \
            _Pragma("unroll")                                                  \
            for (int j = 0; j < 8; j++) acc[i][j] += a[i] * b[j];              \
    }                                                                          \
    __syncthreads();

// ---------------------------------------------------------------------------
// 1) QKV GEMM with embedding gather:  C[m,n] = embed[x[m],:] @ qkv_w + b
//    M=8192, N=1536, K=512
// ---------------------------------------------------------------------------
__global__ __launch_bounds__(256)
void qkv_kernel(const int* __restrict__ x, const float* __restrict__ embed,
                const float* __restrict__ w, const float* __restrict__ bias)
{
    GEMM_PROLOGUE();
    __shared__ int rows[128];
    const int m0 = blockIdx.y * 128;
    const int n0 = blockIdx.x * 128;
    if (tid < 128) rows[tid] = x[m0 + tid];
    __syncthreads();
    const size_t arow = (size_t)rows[ar] * DIM;

    for (int k0 = 0; k0 < DIM; k0 += 8) {
        float4 av = *(const float4*)(embed + arow + k0 + ac);
        As[ac + 0][ar] = av.x; As[ac + 1][ar] = av.y;
        As[ac + 2][ar] = av.z; As[ac + 3][ar] = av.w;
        *(float4*)&Bs[br][bc] =
            *(const float4*)(w + (size_t)(k0 + br) * NQKV + n0 + bc);
        GEMM_COMPUTE();
    }
    #pragma unroll
    for (int i = 0; i < 8; i++) {
        float* crow = g_qkv + (size_t)(m0 + ty * 8 + i) * NQKV + n0 + tx * 8;
        const float* brow = bias + n0 + tx * 8;
        #pragma unroll
        for (int j = 0; j < 8; j += 4) {
            *(float4*)(crow + j) = make_float4(
                acc[i][j + 0] + brow[j + 0], acc[i][j + 1] + brow[j + 1],
                acc[i][j + 2] + brow[j + 2], acc[i][j + 3] + brow[j + 3]);
        }
    }
}

// ---------------------------------------------------------------------------
// 2) scores = Q @ K^T * scale.  Per batch (z). Lower-triangular blocks only.
//    grid: (kTile=16, qTile=16, BATCH)
// ---------------------------------------------------------------------------
__global__ __launch_bounds__(256)
void scores_kernel()
{
    if (blockIdx.x > blockIdx.y) return;   // fully masked block
    GEMM_PROLOGUE();
    const int b  = blockIdx.z;
    const int q0 = blockIdx.y * 128;
    const int n0 = blockIdx.x * 128;       // key index tile
    const float* Q = g_qkv + (size_t)(b * SEQ) * NQKV;         // row stride NQKV
    const float* K = g_qkv + (size_t)(b * SEQ) * NQKV + DIM;   // K at +DIM

    for (int k0 = 0; k0 < DIM; k0 += 8) {
        float4 av = *(const float4*)(Q + (size_t)(q0 + ar) * NQKV + k0 + ac);
        As[ac + 0][ar] = av.x; As[ac + 1][ar] = av.y;
        As[ac + 2][ar] = av.z; As[ac + 3][ar] = av.w;
        // B^T: Bs[kk][n] = K[n0+n][k0+kk]
        float4 bv = *(const float4*)(K + (size_t)(n0 + ar) * NQKV + k0 + ac);
        Bs[ac + 0][ar] = bv.x; Bs[ac + 1][ar] = bv.y;
        Bs[ac + 2][ar] = bv.z; Bs[ac + 3][ar] = bv.w;
        GEMM_COMPUTE();
    }
    const float scale = 0.044194173824159216f;  // 1/sqrt(512)
    #pragma unroll
    for (int i = 0; i < 8; i++) {
        float* crow = g_scores + ((size_t)(b * SEQ + q0 + ty * 8 + i)) * SEQ
                    + n0 + tx * 8;
        #pragma unroll
        for (int j = 0; j < 8; j += 4) {
            *(float4*)(crow + j) = make_float4(
                acc[i][j + 0] * scale, acc[i][j + 1] * scale,
                acc[i][j + 2] * scale, acc[i][j + 3] * scale);
        }
    }
}

// ---------------------------------------------------------------------------
// 3) Row softmax over causal prefix [0..q]; zero masked tail.
//    grid: 8192 rows, 256 threads
// ---------------------------------------------------------------------------
__global__ __launch_bounds__(256)
void softmax_kernel()
{
    const int row = blockIdx.x;            // b*SEQ + q
    const int q = row & (SEQ - 1);
    float* p = g_scores + (size_t)row * SEQ;
    const int L = q + 1;
    const int tid = threadIdx.x;
    __shared__ float red[256];

    float m = -1e30f;
    for (int k = tid; k < L; k += 256) m = fmaxf(m, p[k]);
    red[tid] = m; __syncthreads();
    #pragma unroll
    for (int s = 128; s > 0; s >>= 1) {
        if (tid < s) red[tid] = fmaxf(red[tid], red[tid + s]);
        __syncthreads();
    }
    m = red[0]; __syncthreads();

    float sum = 0.f;
    for (int k = tid; k < L; k += 256) {
        float e = __expf(p[k] - m);
        p[k] = e;
        sum += e;
    }
    red[tid] = sum; __syncthreads();
    #pragma unroll
    for (int s = 128; s > 0; s >>= 1) {
        if (tid < s) red[tid] += red[tid + s];
        __syncthreads();
    }
    const float inv = 1.0f / red[0];
    for (int k = tid; k < L; k += 256) p[k] *= inv;
    for (int k = L + tid; k < SEQ; k += 256) p[k] = 0.f;  // masked tail -> 0
}

// ---------------------------------------------------------------------------
// 4) out = attn @ V.  grid: (nTile=4, qTile=16, BATCH). k truncated at q0+128.
// ---------------------------------------------------------------------------
__global__ __launch_bounds__(256)
void attnv_kernel()
{
    GEMM_PROLOGUE();
    const int b  = blockIdx.z;
    const int q0 = blockIdx.y * 128;
    const int n0 = blockIdx.x * 128;
    const float* A = g_scores + (size_t)(b * SEQ) * SEQ;           // [SEQ,SEQ]
    const float* Vm = g_qkv + (size_t)(b * SEQ) * NQKV + 2 * DIM;  // V at +2D

    const int kend = q0 + 128;   // attn is zero beyond causal boundary
    for (int k0 = 0; k0 < kend; k0 += 8) {
        float4 av = *(const float4*)(A + (size_t)(q0 + ar) * SEQ + k0 + ac);
        As[ac + 0][ar] = av.x; As[ac + 1][ar] = av.y;
        As[ac + 2][ar] = av.z; As[ac + 3][ar] = av.w;
        *(float4*)&Bs[br][bc] =
            *(const float4*)(Vm + (size_t)(k0 + br) * NQKV + n0 + bc);
        GEMM_COMPUTE();
    }
    #pragma unroll
    for (int i = 0; i < 8; i++) {
        float* crow = g_attn_out + (size_t)(b * SEQ + q0 + ty * 8 + i) * DIM
                    + n0 + tx * 8;
        #pragma unroll
        for (int j = 0; j < 8; j += 4)
            *(float4*)(crow + j) = make_float4(acc[i][j + 0], acc[i][j + 1],
                                               acc[i][j + 2], acc[i][j + 3]);
    }
}

// ---------------------------------------------------------------------------
// 5) logits = out @ fc_w + fc_b.  M=8192, N=32000, K=512. grid: (250, 64)
// ---------------------------------------------------------------------------
__global__ __launch_bounds__(256)
void logits_kernel(const float* __restrict__ w, const float* __restrict__ bias,
                   float* __restrict__ out)
{
    GEMM_PROLOGUE();
    const int m0 = blockIdx.y * 128;
    const int n0 = blockIdx.x * 128;

    for (int k0 = 0; k0 < DIM; k0 += 8) {
        float4 av = *(const float4*)(g_attn_out + (size_t)(m0 + ar) * DIM
                                     + k0 + ac);
        As[ac + 0][ar] = av.x; As[ac + 1][ar] = av.y;
        As[ac + 2][ar] = av.z; As[ac + 3][ar] = av.w;
        *(float4*)&Bs[br][bc] =
            *(const float4*)(w + (size_t)(k0 + br) * VOCAB + n0 + bc);
        GEMM_COMPUTE();
    }
    #pragma unroll
    for (int i = 0; i < 8; i++) {
        float* crow = out + (size_t)(m0 + ty * 8 + i) * VOCAB + n0 + tx * 8;
        const float* brow = bias + n0 + tx * 8;
        #pragma unroll
        for (int j = 0; j < 8; j += 4) {
            *(float4*)(crow + j) = make_float4(
                acc[i][j + 0] + brow[j + 0], acc[i][j + 1] + brow[j + 1],
                acc[i][j + 2] + brow[j + 2], acc[i][j + 3] + brow[j + 3]);
        }
    }
}

// ---------------------------------------------------------------------------
extern "C" void kernel_launch(void* const* d_in, const int* in_sizes, int n_in,
                              void* d_out, int out_size)
{
    (void)in_sizes; (void)n_in; (void)out_size;
    const int*   x      = (const int*)  d_in[0];
    const float* embed  = (const float*)d_in[1];
    const float* qkv_w  = (const float*)d_in[2];
    const float* qkv_b  = (const float*)d_in[3];
    const float* fc_w   = (const float*)d_in[4];
    const float* fc_b   = (const float*)d_in[5];
    float* out = (float*)d_out;

    qkv_kernel    <<<dim3(NQKV / 128, MTOK / 128), 256>>>(x, embed, qkv_w, qkv_b);
    scores_kernel <<<dim3(SEQ / 128, SEQ / 128, BATCH), 256>>>();
    softmax_kernel<<<MTOK, 256>>>();
    attnv_kernel  <<<dim3(DIM / 128, SEQ / 128, BATCH), 256>>>();
    logits_kernel <<<dim3(VOCAB / 128, MTOK / 128), 256>>>(fc_w, fc_b, out);
}

// round 3
// speedup vs baseline: 3.0826x; 3.0826x over previous
#include <cuda_runtime.h>
#include <cstdint>
#include <cstddef>

// ---------------------------------------------------------------------------
// TinyTransformer B=4 S=2048 D=512 V=32000 — TF32 tensor-core pipeline.
// All GEMMs: mma.sync.m16n8k8 tf32, 128x128x32 block tile, 8 warps (4x2),
// warp tile 32x64 (2x8 fragments). Smem strides 36 / 136 words give
// conflict-free fragment loads (bank = 4g+t / 8t+g, bijective per warp).
// ---------------------------------------------------------------------------

#define BATCH 4
#define SEQ   2048
#define DIM   512
#define VOCAB 32000
#define NQKV  1536
#define MTOK  8192

#define BM 128
#define BN 128
#define BK 32
#define AST 36     // As row stride (words): bank = (4g+t)%32, conflict-free
#define BST 136    // Bs row stride (words): bank = (8t+g)%32, conflict-free

__device__ float g_qkv[(size_t)MTOK * NQKV];
__device__ float g_scores[(size_t)BATCH * SEQ * SEQ];
__device__ float g_attn_out[(size_t)MTOK * DIM];

__device__ __forceinline__ uint32_t f2tf(float f) {
    uint32_t u;
    asm("cvt.rna.tf32.f32 %0, %1;" : "=r"(u) : "f"(f));
    return u;
}

#define MMA_TF32(c, a, b0, b1)                                                 \
    asm volatile(                                                              \
        "mma.sync.aligned.m16n8k8.row.col.f32.tf32.tf32.f32 "                  \
        "{%0,%1,%2,%3},{%4,%5,%6,%7},{%8,%9},{%0,%1,%2,%3};"                   \
        : "+f"(c[0]), "+f"(c[1]), "+f"(c[2]), "+f"(c[3])                       \
        : "r"(a[0]), "r"(a[1]), "r"(a[2]), "r"(a[3]), "r"(b0), "r"(b1));

#define MMA_PROLOGUE()                                                         \
    const int tid = threadIdx.x;                                               \
    const int lane = tid & 31;                                                 \
    const int wid = tid >> 5;                                                  \
    const int wm = (wid & 3) * 32;                                             \
    const int wn = (wid >> 2) * 64;                                            \
    const int g = lane >> 2;                                                   \
    const int t = lane & 3;                                                    \
    float acc[2][8][4];                                                        \
    _Pragma("unroll")                                                          \
    for (int i = 0; i < 2; i++)                                                \
        _Pragma("unroll")                                                      \
        for (int j = 0; j < 8; j++)                                            \
            _Pragma("unroll")                                                  \
            for (int k = 0; k < 4; k++) acc[i][j][k] = 0.f;

// Compute one BK=32 tile. As: [BM][AST] m-major. Bs: [BK][BST] k-major.
#define TILE_COMPUTE_KN()                                                      \
    _Pragma("unroll")                                                          \
    for (int kk = 0; kk < 4; kk++) {                                           \
        uint32_t af[2][4];                                                     \
        _Pragma("unroll")                                                      \
        for (int mi = 0; mi < 2; mi++) {                                       \
            int mr = wm + mi * 16 + g;                                         \
            af[mi][0] = As[mr * AST + kk * 8 + t];                             \
            af[mi][1] = As[(mr + 8) * AST + kk * 8 + t];                       \
            af[mi][2] = As[mr * AST + kk * 8 + t + 4];                         \
            af[mi][3] = As[(mr + 8) * AST + kk * 8 + t + 4];                   \
        }                                                                      \
        _Pragma("unroll")                                                      \
        for (int ni = 0; ni < 8; ni++) {                                       \
            uint32_t b0 = Bs[(kk * 8 + t) * BST + wn + ni * 8 + g];            \
            uint32_t b1 = Bs[(kk * 8 + t + 4) * BST + wn + ni * 8 + g];        \
            MMA_TF32(acc[0][ni], af[0], b0, b1);                               \
            MMA_TF32(acc[1][ni], af[1], b0, b1);                               \
        }                                                                      \
    }

// Variant: B staged n-major Bs2[BN][AST] (for scores: K rows are n-major).
#define TILE_COMPUTE_NK()                                                      \
    _Pragma("unroll")                                                          \
    for (int kk = 0; kk < 4; kk++) {                                           \
        uint32_t af[2][4];                                                     \
        _Pragma("unroll")                                                      \
        for (int mi = 0; mi < 2; mi++) {                                       \
            int mr = wm + mi * 16 + g;                                         \
            af[mi][0] = As[mr * AST + kk * 8 + t];                             \
            af[mi][1] = As[(mr + 8) * AST + kk * 8 + t];                       \
            af[mi][2] = As[mr * AST + kk * 8 + t + 4];                         \
            af[mi][3] = As[(mr + 8) * AST + kk * 8 + t + 4];                   \
        }                                                                      \
        _Pragma("unroll")                                                      \
        for (int ni = 0; ni < 8; ni++) {                                       \
            int nr = wn + ni * 8 + g;                                          \
            uint32_t b0 = Bs2[nr * AST + kk * 8 + t];                          \
            uint32_t b1 = Bs2[nr * AST + kk * 8 + t + 4];                      \
            MMA_TF32(acc[0][ni], af[0], b0, b1);                               \
            MMA_TF32(acc[1][ni], af[1], b0, b1);                               \
        }                                                                      \
    }

// Stage a 128x32 fp32 tile (rows from `srcrow(r)` pointers) into As as tf32.
#define STAGE_A(PTR_EXPR)                                                      \
    _Pragma("unroll")                                                          \
    for (int i = 0; i < 4; i++) {                                              \
        int v = tid + i * 256, r = v >> 3, kv = (v & 7) * 4;                   \
        float4 f = *(const float4*)(PTR_EXPR);                                 \
        uint4 u = make_uint4(f2tf(f.x), f2tf(f.y), f2tf(f.z), f2tf(f.w));      \
        *(uint4*)&As[r * AST + kv] = u;                                        \
    }

#define STAGE_B(PTR_EXPR)                                                      \
    _Pragma("unroll")                                                          \
    for (int i = 0; i < 4; i++) {                                              \
        int v = tid + i * 256, r = v >> 5, nv = (v & 31) * 4;                  \
        float4 f = *(const float4*)(PTR_EXPR);                                 \
        uint4 u = make_uint4(f2tf(f.x), f2tf(f.y), f2tf(f.z), f2tf(f.w));      \
        *(uint4*)&Bs[r * BST + nv] = u;                                        \
    }

#define STAGE_B_NK(PTR_EXPR)                                                   \
    _Pragma("unroll")                                                          \
    for (int i = 0; i < 4; i++) {                                              \
        int v = tid + i * 256, r = v >> 3, kv = (v & 7) * 4;                   \
        float4 f = *(const float4*)(PTR_EXPR);                                 \
        uint4 u = make_uint4(f2tf(f.x), f2tf(f.y), f2tf(f.z), f2tf(f.w));      \
        *(uint4*)&Bs2[r * AST + kv] = u;                                       \
    }

// ---------------------------------------------------------------------------
// 1) qkv = gather(embed, x) @ qkv_w + b       M=8192 N=1536 K=512
// ---------------------------------------------------------------------------
__global__ __launch_bounds__(256)
void qkv_kernel(const int* __restrict__ x, const float* __restrict__ embed,
                const float* __restrict__ w, const float* __restrict__ bias)
{
    __shared__ uint32_t As[BM * AST];
    __shared__ uint32_t Bs[BK * BST];
    __shared__ int rows[BM];
    MMA_PROLOGUE();
    const int m0 = blockIdx.y * BM;
    const int n0 = blockIdx.x * BN;
    if (tid < BM) rows[tid] = x[m0 + tid];
    __syncthreads();

    for (int k0 = 0; k0 < DIM; k0 += BK) {
        STAGE_A(embed + (size_t)rows[r] * DIM + k0 + kv);
        STAGE_B(w + (size_t)(k0 + r) * NQKV + n0 + nv);
        __syncthreads();
        TILE_COMPUTE_KN();
        __syncthreads();
    }
    #pragma unroll
    for (int mi = 0; mi < 2; mi++)
        #pragma unroll
        for (int ni = 0; ni < 8; ni++) {
            int r0 = m0 + wm + mi * 16 + g;
            int c  = n0 + wn + ni * 8 + t * 2;
            float b0 = bias[c], b1 = bias[c + 1];
            float* p0 = g_qkv + (size_t)r0 * NQKV + c;
            float* p1 = g_qkv + (size_t)(r0 + 8) * NQKV + c;
            *(float2*)p0 = make_float2(acc[mi][ni][0] + b0, acc[mi][ni][1] + b1);
            *(float2*)p1 = make_float2(acc[mi][ni][2] + b0, acc[mi][ni][3] + b1);
        }
}

// ---------------------------------------------------------------------------
// 2) scores = Q @ K^T * scale   (lower-triangular blocks only)
// ---------------------------------------------------------------------------
__global__ __launch_bounds__(256)
void scores_kernel()
{
    if (blockIdx.x > blockIdx.y) return;
    __shared__ uint32_t As[BM * AST];
    __shared__ uint32_t Bs2[BN * AST];
    MMA_PROLOGUE();
    const int b  = blockIdx.z;
    const int q0 = blockIdx.y * BM;
    const int n0 = blockIdx.x * BN;
    const float* Q = g_qkv + (size_t)(b * SEQ) * NQKV;
    const float* K = Q + DIM;

    for (int k0 = 0; k0 < DIM; k0 += BK) {
        STAGE_A(Q + (size_t)(q0 + r) * NQKV + k0 + kv);
        STAGE_B_NK(K + (size_t)(n0 + r) * NQKV + k0 + kv);
        __syncthreads();
        TILE_COMPUTE_NK();
        __syncthreads();
    }
    const float scale = 0.044194173824159216f;
    #pragma unroll
    for (int mi = 0; mi < 2; mi++)
        #pragma unroll
        for (int ni = 0; ni < 8; ni++) {
            int r0 = q0 + wm + mi * 16 + g;
            int c  = n0 + wn + ni * 8 + t * 2;
            float* p0 = g_scores + (size_t)(b * SEQ + r0) * SEQ + c;
            float* p1 = p0 + (size_t)8 * SEQ;
            *(float2*)p0 = make_float2(acc[mi][ni][0] * scale, acc[mi][ni][1] * scale);
            *(float2*)p1 = make_float2(acc[mi][ni][2] * scale, acc[mi][ni][3] * scale);
        }
}

// ---------------------------------------------------------------------------
// 3) causal softmax (prefix [0..q]), zero masked tail
// ---------------------------------------------------------------------------
__global__ __launch_bounds__(256)
void softmax_kernel()
{
    const int row = blockIdx.x;
    const int q = row & (SEQ - 1);
    float* p = g_scores + (size_t)row * SEQ;
    const int L = q + 1;
    const int tid = threadIdx.x;
    __shared__ float red[256];

    float m = -1e30f;
    for (int k = tid; k < L; k += 256) m = fmaxf(m, p[k]);
    red[tid] = m; __syncthreads();
    #pragma unroll
    for (int s = 128; s > 0; s >>= 1) {
        if (tid < s) red[tid] = fmaxf(red[tid], red[tid + s]);
        __syncthreads();
    }
    m = red[0]; __syncthreads();

    float sum = 0.f;
    for (int k = tid; k < L; k += 256) {
        float e = __expf(p[k] - m);
        p[k] = e;
        sum += e;
    }
    red[tid] = sum; __syncthreads();
    #pragma unroll
    for (int s = 128; s > 0; s >>= 1) {
        if (tid < s) red[tid] += red[tid + s];
        __syncthreads();
    }
    const float inv = 1.0f / red[0];
    for (int k = tid; k < L; k += 256) p[k] *= inv;
    for (int k = L + tid; k < SEQ; k += 256) p[k] = 0.f;
}

// ---------------------------------------------------------------------------
// 4) out = attn @ V   (k truncated at causal boundary q0+128)
// ---------------------------------------------------------------------------
__global__ __launch_bounds__(256)
void attnv_kernel()
{
    __shared__ uint32_t As[BM * AST];
    __shared__ uint32_t Bs[BK * BST];
    MMA_PROLOGUE();
    const int b  = blockIdx.z;
    const int q0 = blockIdx.y * BM;
    const int n0 = blockIdx.x * BN;
    const float* A  = g_scores + (size_t)(b * SEQ) * SEQ;
    const float* Vm = g_qkv + (size_t)(b * SEQ) * NQKV + 2 * DIM;

    const int kend = q0 + BM;
    for (int k0 = 0; k0 < kend; k0 += BK) {
        STAGE_A(A + (size_t)(q0 + r) * SEQ + k0 + kv);
        STAGE_B(Vm + (size_t)(k0 + r) * NQKV + n0 + nv);
        __syncthreads();
        TILE_COMPUTE_KN();
        __syncthreads();
    }
    #pragma unroll
    for (int mi = 0; mi < 2; mi++)
        #pragma unroll
        for (int ni = 0; ni < 8; ni++) {
            int r0 = q0 + wm + mi * 16 + g;
            int c  = n0 + wn + ni * 8 + t * 2;
            float* p0 = g_attn_out + (size_t)(b * SEQ + r0) * DIM + c;
            float* p1 = p0 + (size_t)8 * DIM;
            *(float2*)p0 = make_float2(acc[mi][ni][0], acc[mi][ni][1]);
            *(float2*)p1 = make_float2(acc[mi][ni][2], acc[mi][ni][3]);
        }
}

// ---------------------------------------------------------------------------
// 5) logits = out @ fc_w + fc_b    M=8192 N=32000 K=512
// ---------------------------------------------------------------------------
__global__ __launch_bounds__(256)
void logits_kernel(const float* __restrict__ w, const float* __restrict__ bias,
                   float* __restrict__ out)
{
    __shared__ uint32_t As[BM * AST];
    __shared__ uint32_t Bs[BK * BST];
    MMA_PROLOGUE();
    const int m0 = blockIdx.y * BM;
    const int n0 = blockIdx.x * BN;

    for (int k0 = 0; k0 < DIM; k0 += BK) {
        STAGE_A(g_attn_out + (size_t)(m0 + r) * DIM + k0 + kv);
        STAGE_B(w + (size_t)(k0 + r) * VOCAB + n0 + nv);
        __syncthreads();
        TILE_COMPUTE_KN();
        __syncthreads();
    }
    #pragma unroll
    for (int mi = 0; mi < 2; mi++)
        #pragma unroll
        for (int ni = 0; ni < 8; ni++) {
            int r0 = m0 + wm + mi * 16 + g;
            int c  = n0 + wn + ni * 8 + t * 2;
            float b0 = bias[c], b1 = bias[c + 1];
            float* p0 = out + (size_t)r0 * VOCAB + c;
            float* p1 = out + (size_t)(r0 + 8) * VOCAB + c;
            *(float2*)p0 = make_float2(acc[mi][ni][0] + b0, acc[mi][ni][1] + b1);
            *(float2*)p1 = make_float2(acc[mi][ni][2] + b0, acc[mi][ni][3] + b1);
        }
}

// ---------------------------------------------------------------------------
extern "C" void kernel_launch(void* const* d_in, const int* in_sizes, int n_in,
                              void* d_out, int out_size)
{
    (void)in_sizes; (void)n_in; (void)out_size;
    const int*   x     = (const int*)  d_in[0];
    const float* embed = (const float*)d_in[1];
    const float* qkv_w = (const float*)d_in[2];
    const float* qkv_b = (const float*)d_in[3];
    const float* fc_w  = (const float*)d_in[4];
    const float* fc_b  = (const float*)d_in[5];
    float* out = (float*)d_out;

    qkv_kernel    <<<dim3(NQKV / BN, MTOK / BM), 256>>>(x, embed, qkv_w, qkv_b);
    scores_kernel <<<dim3(SEQ / BN, SEQ / BM, BATCH), 256>>>();
    softmax_kernel<<<MTOK, 256>>>();
    attnv_kernel  <<<dim3(DIM / BN, SEQ / BM, BATCH), 256>>>();
    logits_kernel <<<dim3(VOCAB / BN, MTOK / BM), 256>>>(fc_w, fc_b, out);
}

// round 5
// speedup vs baseline: 3.3600x; 1.0900x over previous
#include <cuda_runtime.h>
#include <cstdint>
#include <cstddef>

// ---------------------------------------------------------------------------
// TinyTransformer B=4 S=2048 D=512 V=32000 — TF32 MMA + cp.async pipeline.
// All MMA operands are pre-rounded to tf32 (cvt.rna) at their producer:
// inputs via a round pre-pass into scratch, intermediates in the epilogues.
// cp.async then stages raw bits (already tf32-exact -> no truncation bias).
// ---------------------------------------------------------------------------

#define BATCH 4
#define SEQ   2048
#define DIM   512
#define VOCAB 32000
#define NQKV  1536
#define MTOK  8192

#define BM 128
#define BN 128
#define BK 32
#define AST 36
#define BST 136

__device__ float g_qkv[(size_t)MTOK * NQKV];            // 50.3 MB (rounded)
__device__ float g_scores[(size_t)BATCH * SEQ * SEQ];   // 67.1 MB (fp32/attn)
__device__ float g_attn_out[(size_t)MTOK * DIM];        // 16.8 MB (rounded)
__device__ float g_embed_r[(size_t)VOCAB * DIM];        // 65.5 MB
__device__ float g_qkvw_r[(size_t)DIM * NQKV];          // 3.1 MB
__device__ float g_fcw_r[(size_t)DIM * VOCAB];          // 65.5 MB

__device__ __forceinline__ uint32_t f2tf(float f) {
    uint32_t u;
    asm("cvt.rna.tf32.f32 %0, %1;" : "=r"(u) : "f"(f));
    return u;
}
__device__ __forceinline__ float rnd(float f) { return __uint_as_float(f2tf(f)); }

__device__ __forceinline__ void cpa16(void* s, const float* g) {
    uint32_t sa = (uint32_t)__cvta_generic_to_shared(s);
    asm volatile("cp.async.cg.shared.global [%0], [%1], 16;" :: "r"(sa), "l"(g));
}
#define CP_COMMIT() asm volatile("cp.async.commit_group;")
#define CP_WAIT1()  asm volatile("cp.async.wait_group 1;")

#define MMA_TF32(c, a, b0, b1)                                                 \
    asm volatile(                                                              \
        "mma.sync.aligned.m16n8k8.row.col.f32.tf32.tf32.f32 "                  \
        "{%0,%1,%2,%3},{%4,%5,%6,%7},{%8,%9},{%0,%1,%2,%3};"                   \
        : "+f"(c[0]), "+f"(c[1]), "+f"(c[2]), "+f"(c[3])                       \
        : "r"(a[0]), "r"(a[1]), "r"(a[2]), "r"(a[3]), "r"(b0), "r"(b1));

#define ACC_INIT()                                                             \
    float acc[2][8][4];                                                        \
    _Pragma("unroll")                                                          \
    for (int i = 0; i < 2; i++)                                                \
        _Pragma("unroll")                                                      \
        for (int j = 0; j < 8; j++)                                            \
            _Pragma("unroll")                                                  \
            for (int k = 0; k < 4; k++) acc[i][j][k] = 0.f;

#define TILE_COMPUTE_KN(As, Bs)                                                \
    _Pragma("unroll")                                                          \
    for (int kk = 0; kk < 4; kk++) {                                           \
        uint32_t af[2][4];                                                     \
        _Pragma("unroll")                                                      \
        for (int mi = 0; mi < 2; mi++) {                                       \
            int mr = wm + mi * 16 + g;                                         \
            af[mi][0] = (As)[mr * AST + kk * 8 + t];                           \
            af[mi][1] = (As)[(mr + 8) * AST + kk * 8 + t];                     \
            af[mi][2] = (As)[mr * AST + kk * 8 + t + 4];                       \
            af[mi][3] = (As)[(mr + 8) * AST + kk * 8 + t + 4];                 \
        }                                                                      \
        _Pragma("unroll")                                                      \
        for (int ni = 0; ni < 8; ni++) {                                       \
            uint32_t b0 = (Bs)[(kk * 8 + t) * BST + wn + ni * 8 + g];          \
            uint32_t b1 = (Bs)[(kk * 8 + t + 4) * BST + wn + ni * 8 + g];      \
            MMA_TF32(acc[0][ni], af[0], b0, b1);                               \
            MMA_TF32(acc[1][ni], af[1], b0, b1);                               \
        }                                                                      \
    }

#define TILE_COMPUTE_NK(As, Bs2)                                               \
    _Pragma("unroll")                                                          \
    for (int kk = 0; kk < 4; kk++) {                                           \
        uint32_t af[2][4];                                                     \
        _Pragma("unroll")                                                      \
        for (int mi = 0; mi < 2; mi++) {                                       \
            int mr = wm + mi * 16 + g;                                         \
            af[mi][0] = (As)[mr * AST + kk * 8 + t];                           \
            af[mi][1] = (As)[(mr + 8) * AST + kk * 8 + t];                     \
            af[mi][2] = (As)[mr * AST + kk * 8 + t + 4];                       \
            af[mi][3] = (As)[(mr + 8) * AST + kk * 8 + t + 4];                 \
        }                                                                      \
        _Pragma("unroll")                                                      \
        for (int ni = 0; ni < 8; ni++) {                                       \
            int nr = wn + ni * 8 + g;                                          \
            uint32_t b0 = (Bs2)[nr * AST + kk * 8 + t];                        \
            uint32_t b1 = (Bs2)[nr * AST + kk * 8 + t + 4];                    \
            MMA_TF32(acc[0][ni], af[0], b0, b1);                               \
            MMA_TF32(acc[1][ni], af[1], b0, b1);                               \
        }                                                                      \
    }

#define STAGE_A_ASY(DST, NT, PTR_EXPR)                                         \
    _Pragma("unroll")                                                          \
    for (int i = 0; i < (128 * 32 / 4) / NT; i++) {                            \
        int v = tid + i * NT, r = v >> 3, kv = (v & 7) * 4;                    \
        cpa16((DST) + r * AST + kv, PTR_EXPR);                                 \
    }
#define STAGE_A_ASY_256R(DST, NT, PTR_EXPR)                                    \
    _Pragma("unroll")                                                          \
    for (int i = 0; i < (256 * 32 / 4) / NT; i++) {                            \
        int v = tid + i * NT, r = v >> 3, kv = (v & 7) * 4;                    \
        cpa16((DST) + r * AST + kv, PTR_EXPR);                                 \
    }
#define STAGE_B_ASY(DST, NT, PTR_EXPR)                                         \
    _Pragma("unroll")                                                          \
    for (int i = 0; i < (32 * 128 / 4) / NT; i++) {                            \
        int v = tid + i * NT, r = v >> 5, nv = (v & 31) * 4;                   \
        cpa16((DST) + r * BST + nv, PTR_EXPR);                                 \
    }
#define STAGE_B_NK_ASY(DST, NT, PTR_EXPR)                                      \
    _Pragma("unroll")                                                          \
    for (int i = 0; i < (128 * 32 / 4) / NT; i++) {                            \
        int v = tid + i * NT, r = v >> 3, kv = (v & 7) * 4;                    \
        cpa16((DST) + r * AST + kv, PTR_EXPR);                                 \
    }

// ---------------------------------------------------------------------------
// 0) round pre-pass: dst[i] = tf32_rna(src[i]), vectorized float4
// ---------------------------------------------------------------------------
__global__ __launch_bounds__(256)
void round_kernel(const float* __restrict__ src, float* __restrict__ dst, int n4)
{
    int i = blockIdx.x * 256 + threadIdx.x;
    if (i < n4) {
        float4 f = ((const float4*)src)[i];
        ((uint4*)dst)[i] =
            make_uint4(f2tf(f.x), f2tf(f.y), f2tf(f.z), f2tf(f.w));
    }
}

// ---------------------------------------------------------------------------
// 1) qkv = gather(embed_r, x) @ qkvw_r + b    M=8192 N=1536 K=512
// ---------------------------------------------------------------------------
__global__ __launch_bounds__(256, 2)
void qkv_kernel(const int* __restrict__ x, const float* __restrict__ bias)
{
    extern __shared__ uint32_t sm[];
    int*      rows = (int*)sm;
    uint32_t* Ab   = sm + 128;
    uint32_t* Bb   = Ab + 2 * BM * AST;
    const int tid = threadIdx.x;
    const int lane = tid & 31, wid = tid >> 5;
    const int wm = (wid & 3) * 32, wn = (wid >> 2) * 64;
    const int g = lane >> 2, t = lane & 3;
    ACC_INIT();
    const int m0 = blockIdx.y * BM;
    const int n0 = blockIdx.x * BN;
    if (tid < BM) rows[tid] = x[m0 + tid];
    __syncthreads();

    STAGE_A_ASY(Ab, 256, g_embed_r + (size_t)rows[r] * DIM + kv);
    STAGE_B_ASY(Bb, 256, g_qkvw_r + (size_t)r * NQKV + n0 + nv);
    CP_COMMIT();
    int buf = 0;
    for (int k0 = 0; k0 < DIM; k0 += BK) {
        if (k0 + BK < DIM) {
            uint32_t* An = Ab + (buf ^ 1) * BM * AST;
            uint32_t* Bn = Bb + (buf ^ 1) * BK * BST;
            STAGE_A_ASY(An, 256, g_embed_r + (size_t)rows[r] * DIM + k0 + BK + kv);
            STAGE_B_ASY(Bn, 256, g_qkvw_r + (size_t)(k0 + BK + r) * NQKV + n0 + nv);
        }
        CP_COMMIT();
        CP_WAIT1();
        __syncthreads();
        TILE_COMPUTE_KN(Ab + buf * BM * AST, Bb + buf * BK * BST);
        __syncthreads();
        buf ^= 1;
    }
    #pragma unroll
    for (int mi = 0; mi < 2; mi++)
        #pragma unroll
        for (int ni = 0; ni < 8; ni++) {
            int r0 = m0 + wm + mi * 16 + g;
            int c  = n0 + wn + ni * 8 + t * 2;
            float b0 = bias[c], b1 = bias[c + 1];
            float* p0 = g_qkv + (size_t)r0 * NQKV + c;
            float* p1 = g_qkv + (size_t)(r0 + 8) * NQKV + c;
            *(float2*)p0 = make_float2(rnd(acc[mi][ni][0] + b0),
                                       rnd(acc[mi][ni][1] + b1));
            *(float2*)p1 = make_float2(rnd(acc[mi][ni][2] + b0),
                                       rnd(acc[mi][ni][3] + b1));
        }
}

// ---------------------------------------------------------------------------
// 2) scores = Q @ K^T * scale   (lower-triangular blocks only)
// ---------------------------------------------------------------------------
__global__ __launch_bounds__(256, 2)
void scores_kernel()
{
    if (blockIdx.x > blockIdx.y) return;
    extern __shared__ uint32_t sm[];
    uint32_t* Ab = sm;
    uint32_t* Bb = Ab + 2 * BM * AST;
    const int tid = threadIdx.x;
    const int lane = tid & 31, wid = tid >> 5;
    const int wm = (wid & 3) * 32, wn = (wid >> 2) * 64;
    const int g = lane >> 2, t = lane & 3;
    ACC_INIT();
    const int b  = blockIdx.z;
    const int q0 = blockIdx.y * BM;
    const int n0 = blockIdx.x * BN;
    const float* Q = g_qkv + (size_t)(b * SEQ) * NQKV;
    const float* K = Q + DIM;

    STAGE_A_ASY(Ab, 256, Q + (size_t)(q0 + r) * NQKV + kv);
    STAGE_B_NK_ASY(Bb, 256, K + (size_t)(n0 + r) * NQKV + kv);
    CP_COMMIT();
    int buf = 0;
    for (int k0 = 0; k0 < DIM; k0 += BK) {
        if (k0 + BK < DIM) {
            uint32_t* An = Ab + (buf ^ 1) * BM * AST;
            uint32_t* Bn = Bb + (buf ^ 1) * BM * AST;
            STAGE_A_ASY(An, 256, Q + (size_t)(q0 + r) * NQKV + k0 + BK + kv);
            STAGE_B_NK_ASY(Bn, 256, K + (size_t)(n0 + r) * NQKV + k0 + BK + kv);
        }
        CP_COMMIT();
        CP_WAIT1();
        __syncthreads();
        TILE_COMPUTE_NK(Ab + buf * BM * AST, Bb + buf * BM * AST);
        __syncthreads();
        buf ^= 1;
    }
    const float scale = 0.044194173824159216f;
    #pragma unroll
    for (int mi = 0; mi < 2; mi++)
        #pragma unroll
        for (int ni = 0; ni < 8; ni++) {
            int r0 = q0 + wm + mi * 16 + g;
            int c  = n0 + wn + ni * 8 + t * 2;
            float* p0 = g_scores + (size_t)(b * SEQ + r0) * SEQ + c;
            float* p1 = p0 + (size_t)8 * SEQ;
            *(float2*)p0 = make_float2(acc[mi][ni][0] * scale, acc[mi][ni][1] * scale);
            *(float2*)p1 = make_float2(acc[mi][ni][2] * scale, acc[mi][ni][3] * scale);
        }
}

// ---------------------------------------------------------------------------
// 3) causal softmax; attn stored tf32-rounded; masked tail zeroed
// ---------------------------------------------------------------------------
__global__ __launch_bounds__(256)
void softmax_kernel()
{
    const int row = blockIdx.x;
    const int q = row & (SEQ - 1);
    float* p = g_scores + (size_t)row * SEQ;
    const int L = q + 1;
    const int tid = threadIdx.x;
    const int lane = tid & 31, wid = tid >> 5;
    __shared__ float red[8];

    float m = -1e30f;
    for (int k = tid; k < L; k += 256) m = fmaxf(m, p[k]);
    #pragma unroll
    for (int s = 16; s > 0; s >>= 1) m = fmaxf(m, __shfl_xor_sync(~0u, m, s));
    if (lane == 0) red[wid] = m;
    __syncthreads();
    m = red[lane & 7];
    #pragma unroll
    for (int s = 4; s > 0; s >>= 1) m = fmaxf(m, __shfl_xor_sync(~0u, m, s));

    float sum = 0.f;
    for (int k = tid; k < L; k += 256) {
        float e = __expf(p[k] - m);
        p[k] = e;
        sum += e;
    }
    #pragma unroll
    for (int s = 16; s > 0; s >>= 1) sum += __shfl_xor_sync(~0u, sum, s);
    __syncthreads();
    if (lane == 0) red[wid] = sum;
    __syncthreads();
    sum = red[lane & 7];
    #pragma unroll
    for (int s = 4; s > 0; s >>= 1) sum += __shfl_xor_sync(~0u, sum, s);

    const float inv = 1.0f / sum;
    for (int k = tid; k < L; k += 256) p[k] = rnd(p[k] * inv);
    for (int k = L + tid; k < SEQ; k += 256) p[k] = 0.f;
}

// ---------------------------------------------------------------------------
// 4) out = attn @ V   (k truncated at causal boundary q0+128)
// ---------------------------------------------------------------------------
__global__ __launch_bounds__(256, 2)
void attnv_kernel()
{
    extern __shared__ uint32_t sm[];
    uint32_t* Ab = sm;
    uint32_t* Bb = Ab + 2 * BM * AST;
    const int tid = threadIdx.x;
    const int lane = tid & 31, wid = tid >> 5;
    const int wm = (wid & 3) * 32, wn = (wid >> 2) * 64;
    const int g = lane >> 2, t = lane & 3;
    ACC_INIT();
    const int b  = blockIdx.z;
    const int q0 = blockIdx.y * BM;
    const int n0 = blockIdx.x * BN;
    const float* A  = g_scores + (size_t)(b * SEQ) * SEQ;
    const float* Vm = g_qkv + (size_t)(b * SEQ) * NQKV + 2 * DIM;

    STAGE_A_ASY(Ab, 256, A + (size_t)(q0 + r) * SEQ + kv);
    STAGE_B_ASY(Bb, 256, Vm + (size_t)r * NQKV + n0 + nv);
    CP_COMMIT();
    int buf = 0;
    const int kend = q0 + BM;
    for (int k0 = 0; k0 < kend; k0 += BK) {
        if (k0 + BK < kend) {
            uint32_t* An = Ab + (buf ^ 1) * BM * AST;
            uint32_t* Bn = Bb + (buf ^ 1) * BK * BST;
            STAGE_A_ASY(An, 256, A + (size_t)(q0 + r) * SEQ + k0 + BK + kv);
            STAGE_B_ASY(Bn, 256, Vm + (size_t)(k0 + BK + r) * NQKV + n0 + nv);
        }
        CP_COMMIT();
        CP_WAIT1();
        __syncthreads();
        TILE_COMPUTE_KN(Ab + buf * BM * AST, Bb + buf * BK * BST);
        __syncthreads();
        buf ^= 1;
    }
    #pragma unroll
    for (int mi = 0; mi < 2; mi++)
        #pragma unroll
        for (int ni = 0; ni < 8; ni++) {
            int r0 = q0 + wm + mi * 16 + g;
            int c  = n0 + wn + ni * 8 + t * 2;
            float* p0 = g_attn_out + (size_t)(b * SEQ + r0) * DIM + c;
            float* p1 = p0 + (size_t)8 * DIM;
            *(float2*)p0 = make_float2(rnd(acc[mi][ni][0]), rnd(acc[mi][ni][1]));
            *(float2*)p1 = make_float2(rnd(acc[mi][ni][2]), rnd(acc[mi][ni][3]));
        }
}

// ---------------------------------------------------------------------------
// 5) logits = attn_out @ fcw_r + fc_b    M=8192 N=32000 K=512
//    256x128 tile, 512 threads (8m x 2n warps), warp tile 32x64.
// ---------------------------------------------------------------------------
#define LBM 256
__global__ __launch_bounds__(512, 1)
void logits_kernel(const float* __restrict__ bias, float* __restrict__ out)
{
    extern __shared__ uint32_t sm[];
    uint32_t* Ab = sm;
    uint32_t* Bb = Ab + 2 * LBM * AST;
    const int tid = threadIdx.x;
    const int lane = tid & 31, wid = tid >> 5;
    const int wm = (wid & 7) * 32, wn = (wid >> 3) * 64;
    const int g = lane >> 2, t = lane & 3;
    ACC_INIT();
    const int m0 = blockIdx.y * LBM;
    const int n0 = blockIdx.x * BN;

    STAGE_A_ASY_256R(Ab, 512, g_attn_out + (size_t)(m0 + r) * DIM + kv);
    STAGE_B_ASY(Bb, 512, g_fcw_r + (size_t)r * VOCAB + n0 + nv);
    CP_COMMIT();
    int buf = 0;
    for (int k0 = 0; k0 < DIM; k0 += BK) {
        if (k0 + BK < DIM) {
            uint32_t* An = Ab + (buf ^ 1) * LBM * AST;
            uint32_t* Bn = Bb + (buf ^ 1) * BK * BST;
            STAGE_A_ASY_256R(An, 512,
                g_attn_out + (size_t)(m0 + r) * DIM + k0 + BK + kv);
            STAGE_B_ASY(Bn, 512, g_fcw_r + (size_t)(k0 + BK + r) * VOCAB + n0 + nv);
        }
        CP_COMMIT();
        CP_WAIT1();
        __syncthreads();
        TILE_COMPUTE_KN(Ab + buf * LBM * AST, Bb + buf * BK * BST);
        __syncthreads();
        buf ^= 1;
    }
    #pragma unroll
    for (int mi = 0; mi < 2; mi++)
        #pragma unroll
        for (int ni = 0; ni < 8; ni++) {
            int r0 = m0 + wm + mi * 16 + g;
            int c  = n0 + wn + ni * 8 + t * 2;
            float b0 = bias[c], b1 = bias[c + 1];
            float* p0 = out + (size_t)r0 * VOCAB + c;
            float* p1 = out + (size_t)(r0 + 8) * VOCAB + c;
            *(float2*)p0 = make_float2(acc[mi][ni][0] + b0, acc[mi][ni][1] + b1);
            *(float2*)p1 = make_float2(acc[mi][ni][2] + b0, acc[mi][ni][3] + b1);
        }
}

// ---------------------------------------------------------------------------
extern "C" void kernel_launch(void* const* d_in, const int* in_sizes, int n_in,
                              void* d_out, int out_size)
{
    (void)in_sizes; (void)n_in; (void)out_size;
    const int*   x     = (const int*)  d_in[0];
    const float* embed = (const float*)d_in[1];
    const float* qkv_w = (const float*)d_in[2];
    const float* qkv_b = (const float*)d_in[3];
    const float* fc_w  = (const float*)d_in[4];
    const float* fc_b  = (const float*)d_in[5];
    float* out = (float*)d_out;

    const int smem_qkv    = (128 + 2 * BM * AST + 2 * BK * BST) * 4;
    const int smem_scores = (2 * BM * AST + 2 * BM * AST) * 4;
    const int smem_attnv  = (2 * BM * AST + 2 * BK * BST) * 4;
    const int smem_logits = (2 * LBM * AST + 2 * BK * BST) * 4;

    cudaFuncSetAttribute(qkv_kernel,
        cudaFuncAttributeMaxDynamicSharedMemorySize, smem_qkv);
    cudaFuncSetAttribute(scores_kernel,
        cudaFuncAttributeMaxDynamicSharedMemorySize, smem_scores);
    cudaFuncSetAttribute(attnv_kernel,
        cudaFuncAttributeMaxDynamicSharedMemorySize, smem_attnv);
    cudaFuncSetAttribute(logits_kernel,
        cudaFuncAttributeMaxDynamicSharedMemorySize, smem_logits);

    // pre-round weight/embedding operands into scratch (tf32-exact fp32)
    float* emb_dst;  cudaGetSymbolAddress((void**)&emb_dst,  g_embed_r);
    float* qkvw_dst; cudaGetSymbolAddress((void**)&qkvw_dst, g_qkvw_r);
    float* fcw_dst;  cudaGetSymbolAddress((void**)&fcw_dst,  g_fcw_r);
    const int n4_emb  = VOCAB * DIM / 4;
    const int n4_qkvw = DIM * NQKV / 4;
    const int n4_fcw  = DIM * VOCAB / 4;
    round_kernel<<<(n4_emb  + 255) / 256, 256>>>(embed, emb_dst,  n4_emb);
    round_kernel<<<(n4_qkvw + 255) / 256, 256>>>(qkv_w, qkvw_dst, n4_qkvw);
    round_kernel<<<(n4_fcw  + 255) / 256, 256>>>(fc_w,  fcw_dst,  n4_fcw);

    qkv_kernel    <<<dim3(NQKV / BN, MTOK / BM), 256, smem_qkv>>>(x, qkv_b);
    scores_kernel <<<dim3(SEQ / BN, SEQ / BM, BATCH), 256, smem_scores>>>();
    softmax_kernel<<<MTOK, 256>>>();
    attnv_kernel  <<<dim3(DIM / BN, SEQ / BM, BATCH), 256, smem_attnv>>>();
    logits_kernel <<<dim3(VOCAB / BN, MTOK / LBM), 512, smem_logits>>>(fc_b, out);
}

// round 8
// speedup vs baseline: 3.5853x; 1.0671x over previous
#include <cuda_runtime.h>
#include <cstdint>
#include <cstddef>

// ---------------------------------------------------------------------------
// TinyTransformer B=4 S=2048 D=512 V=32000 — legacy tf32 mma.sync (sm_103
// PTX target: no tcgen05 available from this harness's compile line).
// Single-sync double-buffered cp.async pipeline:
//   wait_group 0 -> syncthreads -> stage(c+1, other buf) -> compute(c)
// logits: BK=64 chunks (8 syncs total), 256x128 tile, 512 threads.
// All MMA operands pre-rounded to tf32 at their producer.
// ---------------------------------------------------------------------------

#define BATCH 4
#define SEQ   2048
#define DIM   512
#define VOCAB 32000
#define NQKV  1536
#define MTOK  8192

#define BM 128
#define BN 128
#define BK 32
#define AST 36     // bank(4g+t) bijective
#define BST 136    // bank(8t+g) bijective

__device__ float g_qkv[(size_t)MTOK * NQKV];
__device__ float g_scores[(size_t)BATCH * SEQ * SEQ];
__device__ float g_attn_out[(size_t)MTOK * DIM];
__device__ float g_embed_r[(size_t)VOCAB * DIM];
__device__ float g_qkvw_r[(size_t)DIM * NQKV];
__device__ float g_fcw_r[(size_t)DIM * VOCAB];

__device__ __forceinline__ uint32_t f2tf(float f) {
    uint32_t u;
    asm("cvt.rna.tf32.f32 %0, %1;" : "=r"(u) : "f"(f));
    return u;
}
__device__ __forceinline__ float rnd(float f) { return __uint_as_float(f2tf(f)); }

__device__ __forceinline__ void cpa16(void* s, const float* g) {
    uint32_t sa = (uint32_t)__cvta_generic_to_shared(s);
    asm volatile("cp.async.cg.shared.global [%0], [%1], 16;" :: "r"(sa), "l"(g));
}
#define CP_COMMIT() asm volatile("cp.async.commit_group;")
#define CP_WAIT0()  asm volatile("cp.async.wait_group 0;")

#define MMA_TF32(c, a, b0, b1)                                                 \
    asm volatile(                                                              \
        "mma.sync.aligned.m16n8k8.row.col.f32.tf32.tf32.f32 "                  \
        "{%0,%1,%2,%3},{%4,%5,%6,%7},{%8,%9},{%0,%1,%2,%3};"                   \
        : "+f"(c[0]), "+f"(c[1]), "+f"(c[2]), "+f"(c[3])                       \
        : "r"(a[0]), "r"(a[1]), "r"(a[2]), "r"(a[3]), "r"(b0), "r"(b1));

#define ACC_INIT()                                                             \
    float acc[2][8][4];                                                        \
    _Pragma("unroll")                                                          \
    for (int i = 0; i < 2; i++)                                                \
        _Pragma("unroll")                                                      \
        for (int j = 0; j < 8; j++)                                            \
            _Pragma("unroll")                                                  \
            for (int k = 0; k < 4; k++) acc[i][j][k] = 0.f;

// Compute one BK=32 tile. As: [rows][AST] m-major. Bs: [32][BST] k-major.
#define TILE_COMPUTE_KN(As, Bs)                                                \
    _Pragma("unroll")                                                          \
    for (int kk = 0; kk < 4; kk++) {                                           \
        uint32_t af[2][4];                                                     \
        _Pragma("unroll")                                                      \
        for (int mi = 0; mi < 2; mi++) {                                       \
            int mr = wm + mi * 16 + g;                                         \
            af[mi][0] = (As)[mr * AST + kk * 8 + t];                           \
            af[mi][1] = (As)[(mr + 8) * AST + kk * 8 + t];                     \
            af[mi][2] = (As)[mr * AST + kk * 8 + t + 4];                       \
            af[mi][3] = (As)[(mr + 8) * AST + kk * 8 + t + 4];                 \
        }                                                                      \
        _Pragma("unroll")                                                      \
        for (int ni = 0; ni < 8; ni++) {                                       \
            uint32_t b0 = (Bs)[(kk * 8 + t) * BST + wn + ni * 8 + g];          \
            uint32_t b1 = (Bs)[(kk * 8 + t + 4) * BST + wn + ni * 8 + g];      \
            MMA_TF32(acc[0][ni], af[0], b0, b1);                               \
            MMA_TF32(acc[1][ni], af[1], b0, b1);                               \
        }                                                                      \
    }

// B staged n-major [BN][AST] (scores: K rows n-major).
#define TILE_COMPUTE_NK(As, Bs2)                                               \
    _Pragma("unroll")                                                          \
    for (int kk = 0; kk < 4; kk++) {                                           \
        uint32_t af[2][4];                                                     \
        _Pragma("unroll")                                                      \
        for (int mi = 0; mi < 2; mi++) {                                       \
            int mr = wm + mi * 16 + g;                                         \
            af[mi][0] = (As)[mr * AST + kk * 8 + t];                           \
            af[mi][1] = (As)[(mr + 8) * AST + kk * 8 + t];                     \
            af[mi][2] = (As)[mr * AST + kk * 8 + t + 4];                       \
            af[mi][3] = (As)[(mr + 8) * AST + kk * 8 + t + 4];                 \
        }                                                                      \
        _Pragma("unroll")                                                      \
        for (int ni = 0; ni < 8; ni++) {                                       \
            int nr = wn + ni * 8 + g;                                          \
            uint32_t b0 = (Bs2)[nr * AST + kk * 8 + t];                        \
            uint32_t b1 = (Bs2)[nr * AST + kk * 8 + t + 4];                    \
            MMA_TF32(acc[0][ni], af[0], b0, b1);                               \
            MMA_TF32(acc[1][ni], af[1], b0, b1);                               \
        }                                                                      \
    }

#define STAGE_A_ASY(DST, NT, PTR_EXPR)                                         \
    _Pragma("unroll")                                                          \
    for (int i = 0; i < (128 * 32 / 4) / NT; i++) {                            \
        int v = tid + i * NT, r = v >> 3, kv = (v & 7) * 4;                    \
        cpa16((DST) + r * AST + kv, PTR_EXPR);                                 \
    }
#define STAGE_B_ASY(DST, NT, PTR_EXPR)                                         \
    _Pragma("unroll")                                                          \
    for (int i = 0; i < (32 * 128 / 4) / NT; i++) {                            \
        int v = tid + i * NT, r = v >> 5, nv = (v & 31) * 4;                   \
        cpa16((DST) + r * BST + nv, PTR_EXPR);                                 \
    }
#define STAGE_B_NK_ASY(DST, NT, PTR_EXPR)                                      \
    _Pragma("unroll")                                                          \
    for (int i = 0; i < (128 * 32 / 4) / NT; i++) {                            \
        int v = tid + i * NT, r = v >> 3, kv = (v & 7) * 4;                    \
        cpa16((DST) + r * AST + kv, PTR_EXPR);                                 \
    }

// ---------------------------------------------------------------------------
// 0) round pre-pass: dst[i] = tf32_rna(src[i])
// ---------------------------------------------------------------------------
__global__ __launch_bounds__(256)
void round_kernel(const float* __restrict__ src, float* __restrict__ dst, int n4)
{
    int i = blockIdx.x * 256 + threadIdx.x;
    if (i < n4) {
        float4 f = ((const float4*)src)[i];
        ((uint4*)dst)[i] = make_uint4(f2tf(f.x), f2tf(f.y), f2tf(f.z), f2tf(f.w));
    }
}

// ---------------------------------------------------------------------------
// 1) qkv = gather(embed_r, x) @ qkvw_r + b    M=8192 N=1536 K=512
// ---------------------------------------------------------------------------
__global__ __launch_bounds__(256, 2)
void qkv_kernel(const int* __restrict__ x, const float* __restrict__ bias)
{
    extern __shared__ uint32_t sm[];
    int*      rows = (int*)sm;
    uint32_t* Ab   = sm + 128;
    uint32_t* Bb   = Ab + 2 * BM * AST;
    const int tid = threadIdx.x;
    const int lane = tid & 31, wid = tid >> 5;
    const int wm = (wid & 3) * 32, wn = (wid >> 2) * 64;
    const int g = lane >> 2, t = lane & 3;
    ACC_INIT();
    const int m0 = blockIdx.y * BM;
    const int n0 = blockIdx.x * BN;
    if (tid < BM) rows[tid] = x[m0 + tid];
    __syncthreads();

    STAGE_A_ASY(Ab, 256, g_embed_r + (size_t)rows[r] * DIM + kv);
    STAGE_B_ASY(Bb, 256, g_qkvw_r + (size_t)r * NQKV + n0 + nv);
    CP_COMMIT();

    for (int c = 0; c < 16; c++) {
        const int b = c & 1;
        CP_WAIT0();
        __syncthreads();
        if (c + 1 < 16) {
            const int k1 = (c + 1) * BK;
            uint32_t* An = Ab + (b ^ 1) * BM * AST;
            uint32_t* Bn = Bb + (b ^ 1) * BK * BST;
            STAGE_A_ASY(An, 256, g_embed_r + (size_t)rows[r] * DIM + k1 + kv);
            STAGE_B_ASY(Bn, 256, g_qkvw_r + (size_t)(k1 + r) * NQKV + n0 + nv);
            CP_COMMIT();
        }
        TILE_COMPUTE_KN(Ab + b * BM * AST, Bb + b * BK * BST);
    }
    #pragma unroll
    for (int mi = 0; mi < 2; mi++)
        #pragma unroll
        for (int ni = 0; ni < 8; ni++) {
            int r0 = m0 + wm + mi * 16 + g;
            int c  = n0 + wn + ni * 8 + t * 2;
            float b0 = bias[c], b1 = bias[c + 1];
            float* p0 = g_qkv + (size_t)r0 * NQKV + c;
            float* p1 = g_qkv + (size_t)(r0 + 8) * NQKV + c;
            *(float2*)p0 = make_float2(rnd(acc[mi][ni][0] + b0),
                                       rnd(acc[mi][ni][1] + b1));
            *(float2*)p1 = make_float2(rnd(acc[mi][ni][2] + b0),
                                       rnd(acc[mi][ni][3] + b1));
        }
}

// ---------------------------------------------------------------------------
// 2) scores = Q @ K^T * scale   (lower-triangular blocks only)
// ---------------------------------------------------------------------------
__global__ __launch_bounds__(256, 2)
void scores_kernel()
{
    if (blockIdx.x > blockIdx.y) return;
    extern __shared__ uint32_t sm[];
    uint32_t* Ab = sm;
    uint32_t* Bb = Ab + 2 * BM * AST;
    const int tid = threadIdx.x;
    const int lane = tid & 31, wid = tid >> 5;
    const int wm = (wid & 3) * 32, wn = (wid >> 2) * 64;
    const int g = lane >> 2, t = lane & 3;
    ACC_INIT();
    const int b  = blockIdx.z;
    const int q0 = blockIdx.y * BM;
    const int n0 = blockIdx.x * BN;
    const float* Q = g_qkv + (size_t)(b * SEQ) * NQKV;
    const float* K = Q + DIM;

    STAGE_A_ASY(Ab, 256, Q + (size_t)(q0 + r) * NQKV + kv);
    STAGE_B_NK_ASY(Bb, 256, K + (size_t)(n0 + r) * NQKV + kv);
    CP_COMMIT();

    for (int c = 0; c < 16; c++) {
        const int bf = c & 1;
        CP_WAIT0();
        __syncthreads();
        if (c + 1 < 16) {
            const int k1 = (c + 1) * BK;
            uint32_t* An = Ab + (bf ^ 1) * BM * AST;
            uint32_t* Bn = Bb + (bf ^ 1) * BM * AST;
            STAGE_A_ASY(An, 256, Q + (size_t)(q0 + r) * NQKV + k1 + kv);
            STAGE_B_NK_ASY(Bn, 256, K + (size_t)(n0 + r) * NQKV + k1 + kv);
            CP_COMMIT();
        }
        TILE_COMPUTE_NK(Ab + bf * BM * AST, Bb + bf * BM * AST);
    }
    const float scale = 0.044194173824159216f;
    #pragma unroll
    for (int mi = 0; mi < 2; mi++)
        #pragma unroll
        for (int ni = 0; ni < 8; ni++) {
            int r0 = q0 + wm + mi * 16 + g;
            int c  = n0 + wn + ni * 8 + t * 2;
            float* p0 = g_scores + (size_t)(b * SEQ + r0) * SEQ + c;
            float* p1 = p0 + (size_t)8 * SEQ;
            *(float2*)p0 = make_float2(acc[mi][ni][0] * scale, acc[mi][ni][1] * scale);
            *(float2*)p1 = make_float2(acc[mi][ni][2] * scale, acc[mi][ni][3] * scale);
        }
}

// ---------------------------------------------------------------------------
// 3) causal softmax; attn stored tf32-rounded; masked tail zeroed
// ---------------------------------------------------------------------------
__global__ __launch_bounds__(256)
void softmax_kernel()
{
    const int row = blockIdx.x;
    const int q = row & (SEQ - 1);
    float* p = g_scores + (size_t)row * SEQ;
    const int L = q + 1;
    const int tid = threadIdx.x;
    const int lane = tid & 31, wid = tid >> 5;
    __shared__ float red[8];

    float m = -1e30f;
    for (int k = tid; k < L; k += 256) m = fmaxf(m, p[k]);
    #pragma unroll
    for (int s = 16; s > 0; s >>= 1) m = fmaxf(m, __shfl_xor_sync(~0u, m, s));
    if (lane == 0) red[wid] = m;
    __syncthreads();
    m = red[lane & 7];
    #pragma unroll
    for (int s = 4; s > 0; s >>= 1) m = fmaxf(m, __shfl_xor_sync(~0u, m, s));

    float sum = 0.f;
    for (int k = tid; k < L; k += 256) {
        float e = __expf(p[k] - m);
        p[k] = e;
        sum += e;
    }
    #pragma unroll
    for (int s = 16; s > 0; s >>= 1) sum += __shfl_xor_sync(~0u, sum, s);
    __syncthreads();
    if (lane == 0) red[wid] = sum;
    __syncthreads();
    sum = red[lane & 7];
    #pragma unroll
    for (int s = 4; s > 0; s >>= 1) sum += __shfl_xor_sync(~0u, sum, s);

    const float inv = 1.0f / sum;
    for (int k = tid; k < L; k += 256) p[k] = rnd(p[k] * inv);
    for (int k = L + tid; k < SEQ; k += 256) p[k] = 0.f;
}

// ---------------------------------------------------------------------------
// 4) out = attn @ V   (k truncated at causal boundary q0+128)
// ---------------------------------------------------------------------------
__global__ __launch_bounds__(256, 2)
void attnv_kernel()
{
    extern __shared__ uint32_t sm[];
    uint32_t* Ab = sm;
    uint32_t* Bb = Ab + 2 * BM * AST;
    const int tid = threadIdx.x;
    const int lane = tid & 31, wid = tid >> 5;
    const int wm = (wid & 3) * 32, wn = (wid >> 2) * 64;
    const int g = lane >> 2, t = lane & 3;
    ACC_INIT();
    const int b  = blockIdx.z;
    const int q0 = blockIdx.y * BM;
    const int n0 = blockIdx.x * BN;
    const float* A  = g_scores + (size_t)(b * SEQ) * SEQ;
    const float* Vm = g_qkv + (size_t)(b * SEQ) * NQKV + 2 * DIM;

    STAGE_A_ASY(Ab, 256, A + (size_t)(q0 + r) * SEQ + kv);
    STAGE_B_ASY(Bb, 256, Vm + (size_t)r * NQKV + n0 + nv);
    CP_COMMIT();

    const int NC = (q0 + BM) / BK;
    for (int c = 0; c < NC; c++) {
        const int bf = c & 1;
        CP_WAIT0();
        __syncthreads();
        if (c + 1 < NC) {
            const int k1 = (c + 1) * BK;
            uint32_t* An = Ab + (bf ^ 1) * BM * AST;
            uint32_t* Bn = Bb + (bf ^ 1) * BK * BST;
            STAGE_A_ASY(An, 256, A + (size_t)(q0 + r) * SEQ + k1 + kv);
            STAGE_B_ASY(Bn, 256, Vm + (size_t)(k1 + r) * NQKV + n0 + nv);
            CP_COMMIT();
        }
        TILE_COMPUTE_KN(Ab + bf * BM * AST, Bb + bf * BK * BST);
    }
    #pragma unroll
    for (int mi = 0; mi < 2; mi++)
        #pragma unroll
        for (int ni = 0; ni < 8; ni++) {
            int r0 = q0 + wm + mi * 16 + g;
            int c  = n0 + wn + ni * 8 + t * 2;
            float* p0 = g_attn_out + (size_t)(b * SEQ + r0) * DIM + c;
            float* p1 = p0 + (size_t)8 * DIM;
            *(float2*)p0 = make_float2(rnd(acc[mi][ni][0]), rnd(acc[mi][ni][1]));
            *(float2*)p1 = make_float2(rnd(acc[mi][ni][2]), rnd(acc[mi][ni][3]));
        }
}

// ---------------------------------------------------------------------------
// 5) logits = attn_out @ fcw_r + fc_b    M=8192 N=32000 K=512
//    256x128 tile, 512 threads (8m x 2n warps), BK=64 chunks (8 total).
//    A: [256][68] (bank 4g+t bijective since 68 % 32 == 4). B: [64][136].
// ---------------------------------------------------------------------------
#define LBM  256
#define LBK  64
#define LAST 68

__global__ __launch_bounds__(512, 1)
void logits_kernel(const float* __restrict__ bias, float* __restrict__ out)
{
    extern __shared__ uint32_t sm[];
    uint32_t* Ab = sm;                        // 2 * LBM*LAST
    uint32_t* Bb = Ab + 2 * LBM * LAST;       // 2 * LBK*BST
    const int tid = threadIdx.x;
    const int lane = tid & 31, wid = tid >> 5;
    const int wm = (wid & 7) * 32, wn = (wid >> 3) * 64;
    const int g = lane >> 2, t = lane & 3;
    ACC_INIT();
    const int m0 = blockIdx.y * LBM;
    const int n0 = blockIdx.x * BN;

    // stage chunk 0: A 256x64, B 64x128
    #pragma unroll
    for (int i = 0; i < 8; i++) {   // 256*64/4 / 512
        int v = tid + i * 512, r = v >> 4, kv = (v & 15) * 4;
        cpa16(Ab + r * LAST + kv, g_attn_out + (size_t)(m0 + r) * DIM + kv);
    }
    #pragma unroll
    for (int i = 0; i < 4; i++) {   // 64*128/4 / 512
        int v = tid + i * 512, r = v >> 5, nv = (v & 31) * 4;
        cpa16(Bb + r * BST + nv, g_fcw_r + (size_t)r * VOCAB + n0 + nv);
    }
    CP_COMMIT();

    for (int c = 0; c < 8; c++) {
        const int bf = c & 1;
        CP_WAIT0();
        __syncthreads();
        if (c + 1 < 8) {
            const int k1 = (c + 1) * LBK;
            uint32_t* An = Ab + (bf ^ 1) * LBM * LAST;
            uint32_t* Bn = Bb + (bf ^ 1) * LBK * BST;
            #pragma unroll
            for (int i = 0; i < 8; i++) {
                int v = tid + i * 512, r = v >> 4, kv = (v & 15) * 4;
                cpa16(An + r * LAST + kv,
                      g_attn_out + (size_t)(m0 + r) * DIM + k1 + kv);
            }
            #pragma unroll
            for (int i = 0; i < 4; i++) {
                int v = tid + i * 512, r = v >> 5, nv = (v & 31) * 4;
                cpa16(Bn + r * BST + nv,
                      g_fcw_r + (size_t)(k1 + r) * VOCAB + n0 + nv);
            }
            CP_COMMIT();
        }
        const uint32_t* As = Ab + bf * LBM * LAST;
        const uint32_t* Bs = Bb + bf * LBK * BST;
        #pragma unroll
        for (int kk = 0; kk < 8; kk++) {
            uint32_t af[2][4];
            #pragma unroll
            for (int mi = 0; mi < 2; mi++) {
                int mr = wm + mi * 16 + g;
                af[mi][0] = As[mr * LAST + kk * 8 + t];
                af[mi][1] = As[(mr + 8) * LAST + kk * 8 + t];
                af[mi][2] = As[mr * LAST + kk * 8 + t + 4];
                af[mi][3] = As[(mr + 8) * LAST + kk * 8 + t + 4];
            }
            #pragma unroll
            for (int ni = 0; ni < 8; ni++) {
                uint32_t b0 = Bs[(kk * 8 + t) * BST + wn + ni * 8 + g];
                uint32_t b1 = Bs[(kk * 8 + t + 4) * BST + wn + ni * 8 + g];
                MMA_TF32(acc[0][ni], af[0], b0, b1);
                MMA_TF32(acc[1][ni], af[1], b0, b1);
            }
        }
    }
    #pragma unroll
    for (int mi = 0; mi < 2; mi++)
        #pragma unroll
        for (int ni = 0; ni < 8; ni++) {
            int r0 = m0 + wm + mi * 16 + g;
            int c  = n0 + wn + ni * 8 + t * 2;
            float b0 = bias[c], b1 = bias[c + 1];
            float* p0 = out + (size_t)r0 * VOCAB + c;
            float* p1 = out + (size_t)(r0 + 8) * VOCAB + c;
            *(float2*)p0 = make_float2(acc[mi][ni][0] + b0, acc[mi][ni][1] + b1);
            *(float2*)p1 = make_float2(acc[mi][ni][2] + b0, acc[mi][ni][3] + b1);
        }
}

// ---------------------------------------------------------------------------
extern "C" void kernel_launch(void* const* d_in, const int* in_sizes, int n_in,
                              void* d_out, int out_size)
{
    (void)in_sizes; (void)n_in; (void)out_size;
    const int*   x     = (const int*)  d_in[0];
    const float* embed = (const float*)d_in[1];
    const float* qkv_w = (const float*)d_in[2];
    const float* qkv_b = (const float*)d_in[3];
    const float* fc_w  = (const float*)d_in[4];
    const float* fc_b  = (const float*)d_in[5];
    float* out = (float*)d_out;

    const int smem_qkv    = (128 + 2 * BM * AST + 2 * BK * BST) * 4;
    const int smem_scores = (2 * BM * AST + 2 * BM * AST) * 4;
    const int smem_attnv  = (2 * BM * AST + 2 * BK * BST) * 4;
    const int smem_logits = (2 * LBM * LAST + 2 * LBK * BST) * 4;   // ~209 KB

    cudaFuncSetAttribute(qkv_kernel,
        cudaFuncAttributeMaxDynamicSharedMemorySize, smem_qkv);
    cudaFuncSetAttribute(scores_kernel,
        cudaFuncAttributeMaxDynamicSharedMemorySize, smem_scores);
    cudaFuncSetAttribute(attnv_kernel,
        cudaFuncAttributeMaxDynamicSharedMemorySize, smem_attnv);
    cudaFuncSetAttribute(logits_kernel,
        cudaFuncAttributeMaxDynamicSharedMemorySize, smem_logits);

    float* emb_dst;  cudaGetSymbolAddress((void**)&emb_dst,  g_embed_r);
    float* qkvw_dst; cudaGetSymbolAddress((void**)&qkvw_dst, g_qkvw_r);
    float* fcw_dst;  cudaGetSymbolAddress((void**)&fcw_dst,  g_fcw_r);
    const int n4_emb  = VOCAB * DIM / 4;
    const int n4_qkvw = DIM * NQKV / 4;
    const int n4_fcw  = DIM * VOCAB / 4;
    round_kernel<<<(n4_emb  + 255) / 256, 256>>>(embed, emb_dst,  n4_emb);
    round_kernel<<<(n4_qkvw + 255) / 256, 256>>>(qkv_w, qkvw_dst, n4_qkvw);
    round_kernel<<<(n4_fcw  + 255) / 256, 256>>>(fc_w,  fcw_dst,  n4_fcw);

    qkv_kernel    <<<dim3(NQKV / BN, MTOK / BM), 256, smem_qkv>>>(x, qkv_b);
    scores_kernel <<<dim3(SEQ / BN, SEQ / BM, BATCH), 256, smem_scores>>>();
    softmax_kernel<<<MTOK, 256>>>();
    attnv_kernel  <<<dim3(DIM / BN, SEQ / BM, BATCH), 256, smem_attnv>>>();
    logits_kernel <<<dim3(VOCAB / BN, MTOK / LBM), 512, smem_logits>>>(fc_b, out);
}